// round 14
// baseline (speedup 1.0000x reference)
#include <cuda_runtime.h>
#include <cuda_fp16.h>
#include <stdint.h>
#include <math.h>

#define NTOK   4096
#define DMODEL 1024
#define DFF    4096
#define NEXP   8
#define NEXPX  9
#define NASSIGN (NTOK*2)
#define NROWS  (NASSIGN + NTOK)
#define SCALE_F 0.894427190999915878f

// ---------------- device scratch ----------------------------------------------------
__device__ __half d_W1x[(size_t)NEXPX * DFF * DMODEL];
__device__ __half d_W2x[(size_t)NEXPX * DMODEL * DFF];
__device__ float  d_b1x[NEXPX * DFF];
__device__ float  d_b2x[NEXPX * DMODEL];
__device__ __half d_xh[(size_t)NTOK * DMODEL];
__device__ __half d_Hh[(size_t)NROWS * DFF];
__device__ float  d_gates[NASSIGN];
__device__ int    d_assign_e[NASSIGN];
__device__ int    d_offsets[NEXPX + 1];
__device__ int    d_rows_token[NROWS];
__device__ float  d_growsc[NROWS];

// ---------------- helpers --------------------------------------------------------------
__device__ __forceinline__ float gelu_tanh(float v) {
    const float c0 = 0.7978845608028654f;
    const float c1 = 0.044715f;
    float t = tanhf(c0 * (v + c1 * v * v * v));
    return 0.5f * v * (1.0f + t);
}

__device__ __forceinline__ void mma16816(float* c, const uint32_t* a, const uint32_t* b) {
    asm volatile(
        "mma.sync.aligned.m16n8k16.row.col.f32.f16.f16.f32 "
        "{%0,%1,%2,%3}, {%4,%5,%6,%7}, {%8,%9}, {%0,%1,%2,%3};"
        : "+f"(c[0]), "+f"(c[1]), "+f"(c[2]), "+f"(c[3])
        : "r"(a[0]), "r"(a[1]), "r"(a[2]), "r"(a[3]), "r"(b[0]), "r"(b[1]));
}

__device__ __forceinline__ void ldsm4(uint32_t* r, uint32_t addr) {
    asm volatile("ldmatrix.sync.aligned.m8n8.x4.shared.b16 {%0,%1,%2,%3}, [%4];"
                 : "=r"(r[0]), "=r"(r[1]), "=r"(r[2]), "=r"(r[3]) : "r"(addr));
}

__device__ __forceinline__ uint32_t smem_u32(const void* p) {
    uint32_t a;
    asm("{ .reg .u64 t; cvta.to.shared.u64 t, %1; cvt.u32.u64 %0, t; }" : "=r"(a) : "l"(p));
    return a;
}

__device__ __forceinline__ void cp16(uint32_t saddr, const void* g, int srcsz) {
    asm volatile("cp.async.cg.shared.global [%0], [%1], 16, %2;"
                 :: "r"(saddr), "l"(g), "r"(srcsz) : "memory");
}
#define CP_COMMIT() asm volatile("cp.async.commit_group;" ::: "memory")
#define CP_WAIT2()  asm volatile("cp.async.wait_group 2;" ::: "memory")

__device__ __forceinline__ void cvt_store(const float4* __restrict__ src, uint2* __restrict__ dst, int i) {
    float4 v = src[i];
    __half2 a = __floats2half2_rn(v.x, v.y);
    __half2 b = __floats2half2_rn(v.z, v.w);
    dst[i] = make_uint2(*(uint32_t*)&a, *(uint32_t*)&b);
}

// ---------------- launch 1: router + W1/x/bias conversion (fused) -------------------------
#define CVT_BLOCKS 4096
__global__ void router_cvt(const float* __restrict__ x,
                           const float* __restrict__ wr,
                           const float4* __restrict__ W1, const float4* __restrict__ Ws1,
                           const float* __restrict__ b1, const float* __restrict__ bs1,
                           const float* __restrict__ b2, const float* __restrict__ bs2,
                           uint2* __restrict__ W1x, uint2* __restrict__ xh,
                           float* __restrict__ b1x, float* __restrict__ b2x) {
    if (blockIdx.x >= NTOK) {
        int idx0 = (blockIdx.x - NTOK) * blockDim.x + threadIdx.x;
        const int nthr = CVT_BLOCKS * 256;
        const int n4r = NEXP * DFF * DMODEL / 4;
        const int n4t = NEXPX * DFF * DMODEL / 4;
        for (int i = idx0; i < n4t; i += nthr) {
            float4 v = (i < n4r) ? W1[i] : Ws1[i - n4r];
            __half2 a = __floats2half2_rn(v.x, v.y);
            __half2 b = __floats2half2_rn(v.z, v.w);
            W1x[i] = make_uint2(*(uint32_t*)&a, *(uint32_t*)&b);
        }
        for (int i = idx0; i < NTOK * DMODEL / 4; i += nthr)
            cvt_store((const float4*)x, xh, i);
        for (int i = idx0; i < NEXPX * DFF; i += nthr)
            b1x[i] = (i < NEXP * DFF) ? b1[i] : bs1[i - NEXP * DFF];
        for (int i = idx0; i < NEXPX * DMODEL; i += nthr)
            b2x[i] = (i < NEXP * DMODEL) ? b2[i] : bs2[i - NEXP * DMODEL];
        return;
    }
    int t = blockIdx.x;
    int warp = threadIdx.x >> 5;
    int lane = threadIdx.x & 31;
    const float* xr = x + (size_t)t * DMODEL;
    const float* w  = wr + (size_t)warp * DMODEL;
    float s = 0.f;
    #pragma unroll 4
    for (int i = lane; i < DMODEL; i += 32) s += xr[i] * w[i];
    #pragma unroll
    for (int o = 16; o > 0; o >>= 1) s += __shfl_xor_sync(0xFFFFFFFFu, s, o);

    __shared__ float logits[NEXP];
    if (warp < NEXP && lane == 0) logits[warp] = s;
    __syncthreads();

    if (threadIdx.x == 0) {
        float mx = logits[0];
        #pragma unroll
        for (int e = 1; e < NEXP; e++) mx = fmaxf(mx, logits[e]);
        float p[NEXP]; float sum = 0.f;
        #pragma unroll
        for (int e = 0; e < NEXP; e++) { p[e] = expf(logits[e] - mx); sum += p[e]; }
        float inv = 1.f / sum;
        #pragma unroll
        for (int e = 0; e < NEXP; e++) p[e] *= inv;
        int i0 = 0;
        #pragma unroll
        for (int e = 1; e < NEXP; e++) if (p[e] > p[i0]) i0 = e;
        int i1 = -1;
        #pragma unroll
        for (int e = 0; e < NEXP; e++) {
            if (e == i0) continue;
            if (i1 < 0 || p[e] > p[i1]) i1 = e;
        }
        d_gates[2 * t + 0] = p[i0];
        d_gates[2 * t + 1] = p[i1];
        d_assign_e[2 * t + 0] = i0;
        d_assign_e[2 * t + 1] = i1;
    }
}

// ---------------- launch 2: single-block count + scan + place ----------------------------
__global__ void scanplace_kernel() {
    __shared__ int scount[NEXP];
    __shared__ int scursor[NEXP];
    int tid = threadIdx.x;
    if (tid < NEXP) scount[tid] = 0;
    __syncthreads();
    for (int a = tid; a < NASSIGN; a += blockDim.x)
        atomicAdd(&scount[d_assign_e[a]], 1);
    __syncthreads();
    if (tid == 0) {
        int s = 0;
        for (int e = 0; e < NEXP; e++) { d_offsets[e] = s; scursor[e] = s; s += scount[e]; }
        d_offsets[NEXP]  = s;
        d_offsets[NEXPX] = NROWS;
    }
    __syncthreads();
    for (int a = tid; a < NASSIGN; a += blockDim.x) {
        int e = d_assign_e[a];
        int r = atomicAdd(&scursor[e], 1);
        d_rows_token[r] = a >> 1;
        d_growsc[r] = SCALE_F * d_gates[a];
    }
    for (int t = tid; t < NTOK; t += blockDim.x) {
        d_rows_token[NASSIGN + t] = t;
        d_growsc[NASSIGN + t] = SCALE_F;
    }
}

// ================= fp16 HMMA grouped GEMM: 256x128x64, 256 thr, 64x64 warp tiles =========
// 8 warps, warp grid 4(m) x 2(n), warp tile 64x64. Crossbar traffic/iter = 128KB ldsm +
// 48KB STS (~1410 cyc) < MMA 2048 cyc -> smem no longer co-binding.
// cp.async 4-stage, distance-3 prefetch, wait_group(2).
#define RS      144
#define T_B     36864             // A: 256 rows x 144B
#define STAGE_B 55296             // + B: 128 rows x 144B
#define NSTAGE  4
#define GEMM_SMEM (NSTAGE * STAGE_B)
#define GTHREADS 256

__global__ __launch_bounds__(GTHREADS, 1)
void gemm_tc(const __half* __restrict__ Ah, int lda, const int* __restrict__ gather,
             const __half* __restrict__ Bh_base, size_t wstride,
             const float* __restrict__ bias_base, size_t bstride,
             __half* __restrict__ Ch, int ldc,
             float* __restrict__ out_at,
             const int* __restrict__ rows_token, const float* __restrict__ growsc,
             const int* __restrict__ offs, int K, int kh_count, int do_gelu,
             const float4* __restrict__ cw8, const float4* __restrict__ cws,
             uint2* __restrict__ cdst, int cn4r, int cn4t)
{
    extern __shared__ char smem[];
    int z = blockIdx.z;
    int nz_gemm = NEXPX * kh_count;
    if (z >= nz_gemm) {
        int idx0 = (blockIdx.y * gridDim.x + blockIdx.x) * blockDim.x + threadIdx.x;
        int nthr = gridDim.x * gridDim.y * blockDim.x;
        for (int i = idx0; i < cn4t; i += nthr) {
            float4 v = (i < cn4r) ? cw8[i] : cws[i - cn4r];
            __half2 a = __floats2half2_rn(v.x, v.y);
            __half2 b = __floats2half2_rn(v.z, v.w);
            cdst[i] = make_uint2(*(uint32_t*)&a, *(uint32_t*)&b);
        }
        return;
    }
    int e  = z / kh_count;
    int kh = z - e * kh_count;
    int Ks = K / kh_count;
    int lo = offs[e];
    int hi = offs[e + 1];
    int m0 = lo + blockIdx.y * 256;
    if (m0 >= hi) return;
    int n0 = blockIdx.x * 128;
    const __half* Bh = Bh_base + (size_t)e * wstride + kh * Ks;
    const float* bias = bias_base + (size_t)e * bstride;

    uint32_t sbase = smem_u32(smem);
    int tid  = threadIdx.x;
    int wid  = tid >> 5;
    int lane = tid & 31;
    int tig  = lane & 3;
    int wm   = wid >> 1;        // 0..3  (M: 4 x 64)
    int wn   = wid & 1;         // 0..1  (N: 2 x 64)

    // ---- cp.async coords: A one full row per thread (8x16B), B half row (4x16B) -------
    int arow = m0 + tid;                 // A row 0..255
    int av16 = (arow < hi) ? 16 : 0;
    int asrc = (arow < hi) ? (gather ? gather[arow] : arow) : 0;
    const char* gA = (const char*)(Ah + (size_t)asrc * lda + kh * Ks);
    uint32_t sA = sbase + (uint32_t)(tid * RS);
    int brow = tid >> 1;
    int bcb  = (tid & 1) * 64;
    const char* gB = (const char*)(Bh + (size_t)(n0 + brow) * K) + bcb;
    uint32_t sB = sbase + (uint32_t)(T_B + brow * RS + bcb);

    // ---- ldmatrix lane offsets ----------------------------------------------------------
    uint32_t aoff[4], boff[8];
    #pragma unroll
    for (int mi = 0; mi < 4; mi++)
        aoff[mi] = (uint32_t)((wm * 64 + mi * 16 + (lane & 15)) * RS + (lane >> 4) * 16);
    #pragma unroll
    for (int ni = 0; ni < 8; ni++)
        boff[ni] = (uint32_t)(T_B + (wn * 64 + ni * 8 + (lane & 7)) * RS + (lane >> 3) * 16);

    float acc[4][8][4];
    #pragma unroll
    for (int mi = 0; mi < 4; mi++)
        #pragma unroll
        for (int ni = 0; ni < 8; ni++)
            #pragma unroll
            for (int q = 0; q < 4; q++) acc[mi][ni][q] = 0.f;

    int nk = Ks >> 6;

    auto issue = [&](int kt, int s) {
        uint32_t so = (uint32_t)(s * STAGE_B);
        int kbyte = kt << 7;
        #pragma unroll
        for (int j = 0; j < 8; j++) cp16(sA + so + j * 16, gA + kbyte + j * 16, av16);
        #pragma unroll
        for (int j = 0; j < 4; j++) cp16(sB + so + j * 16, gB + kbyte + j * 16, 16);
        CP_COMMIT();
    };

    // prologue: 3 stages in flight
    issue(0, 0);
    if (nk > 1) issue(1, 1); else CP_COMMIT();
    if (nk > 2) issue(2, 2); else CP_COMMIT();

    int s = 0;
    for (int kt = 0; kt < nk; kt++) {
        CP_WAIT2();
        __syncthreads();

        if (kt + 3 < nk) issue(kt + 3, (s + 3) & 3);
        else CP_COMMIT();

        uint32_t st = sbase + (uint32_t)(s * STAGE_B);

        uint32_t bhf[8][4];        // B pair (2 ks) for 8 n-tiles
        uint32_t ahf[2][4][4];     // A double buffer
        #pragma unroll
        for (int ni = 0; ni < 8; ni++) ldsm4(bhf[ni], st + boff[ni]);
        #pragma unroll
        for (int mi = 0; mi < 4; mi++) ldsm4(ahf[0][mi], st + aoff[mi]);

        #pragma unroll
        for (int ks = 0; ks < 4; ks++) {
            int cur = ks & 1;
            #pragma unroll
            for (int mi = 0; mi < 4; mi++)
                #pragma unroll
                for (int ni = 0; ni < 8; ni++)
                    mma16816(acc[mi][ni], ahf[cur][mi], &bhf[ni][2 * (ks & 1)]);
            if (ks == 1) {
                #pragma unroll
                for (int ni = 0; ni < 8; ni++) ldsm4(bhf[ni], st + boff[ni] + 64);
            }
            if (ks < 3) {
                #pragma unroll
                for (int mi = 0; mi < 4; mi++) ldsm4(ahf[cur ^ 1][mi], st + aoff[mi] + (ks + 1) * 32);
            }
        }

        s = (s + 1) & 3;
    }

    // ---------------- epilogue ------------------------------------------------------------
    int g = lane >> 2;
    #pragma unroll
    for (int mi = 0; mi < 4; mi++) {
        int row0 = m0 + wm * 64 + mi * 16 + g;
        #pragma unroll
        for (int h = 0; h < 2; h++) {
            int row = row0 + h * 8;
            if (row >= hi) continue;
            if (Ch) {
                #pragma unroll
                for (int ni = 0; ni < 8; ni++) {
                    int cn = n0 + wn * 64 + ni * 8 + tig * 2;
                    float v0 = acc[mi][ni][2 * h + 0] + bias[cn];
                    float v1 = acc[mi][ni][2 * h + 1] + bias[cn + 1];
                    if (do_gelu) { v0 = gelu_tanh(v0); v1 = gelu_tanh(v1); }
                    __half2 hp = __floats2half2_rn(v0, v1);
                    *(uint32_t*)(Ch + (size_t)row * ldc + cn) = *(uint32_t*)&hp;
                }
            } else {
                int tok = rows_token[row];
                float gs = growsc[row];
                float* ob = out_at + (size_t)tok * DMODEL;
                #pragma unroll
                for (int ni = 0; ni < 8; ni++) {
                    int cn = n0 + wn * 64 + ni * 8 + tig * 2;
                    float b0 = (kh == 0) ? bias[cn]     : 0.f;
                    float b1 = (kh == 0) ? bias[cn + 1] : 0.f;
                    atomicAdd(ob + cn,     gs * (acc[mi][ni][2 * h + 0] + b0));
                    atomicAdd(ob + cn + 1, gs * (acc[mi][ni][2 * h + 1] + b1));
                }
            }
        }
    }
}

// ---------------- launcher --------------------------------------------------------------------
extern "C" void kernel_launch(void* const* d_in, const int* in_sizes, int n_in,
                              void* d_out, int out_size)
{
    const float* x   = (const float*)d_in[0];
    const float* wr  = (const float*)d_in[1];
    const float* W1  = (const float*)d_in[2];
    const float* b1  = (const float*)d_in[3];
    const float* W2  = (const float*)d_in[4];
    const float* b2  = (const float*)d_in[5];
    const float* Ws1 = (const float*)d_in[6];
    const float* bs1 = (const float*)d_in[7];
    const float* Ws2 = (const float*)d_in[8];
    const float* bs2 = (const float*)d_in[9];
    float* out = (float*)d_out;

    __half *W1x, *W2x, *xh, *Hh;
    float *b1x, *b2x, *growsc;
    int *offsets, *rows_token;
    cudaGetSymbolAddress((void**)&W1x, d_W1x);
    cudaGetSymbolAddress((void**)&W2x, d_W2x);
    cudaGetSymbolAddress((void**)&b1x, d_b1x);
    cudaGetSymbolAddress((void**)&b2x, d_b2x);
    cudaGetSymbolAddress((void**)&xh, d_xh);
    cudaGetSymbolAddress((void**)&Hh, d_Hh);
    cudaGetSymbolAddress((void**)&growsc, d_growsc);
    cudaGetSymbolAddress((void**)&offsets, d_offsets);
    cudaGetSymbolAddress((void**)&rows_token, d_rows_token);

    cudaFuncSetAttribute(gemm_tc, cudaFuncAttributeMaxDynamicSharedMemorySize, GEMM_SMEM);

    // 1) router + W1/x/bias conversion (fused, overlapped)
    router_cvt<<<NTOK + CVT_BLOCKS, 256>>>(x, wr,
                                           (const float4*)W1, (const float4*)Ws1,
                                           b1, bs1, b2, bs2,
                                           (uint2*)W1x, (uint2*)xh, b1x, b2x);

    // 2) scan + place + gate-scale table
    scanplace_kernel<<<1, 1024>>>();

    // 3) zero output
    cudaMemsetAsync(out, 0, (size_t)NTOK * DMODEL * sizeof(float));

    // 4) up-GEMM (z=0..8) + fused W2 conversion (z=9)
    {
        dim3 g(DFF / 128, 16, NEXPX + 1);
        gemm_tc<<<g, GTHREADS, GEMM_SMEM>>>(xh, DMODEL, rows_token,
                                            W1x, (size_t)DFF * DMODEL, b1x, DFF,
                                            Hh, DFF,
                                            nullptr, nullptr, nullptr,
                                            offsets, DMODEL, 1, 1,
                                            (const float4*)W2, (const float4*)Ws2, (uint2*)W2x,
                                            NEXP * DMODEL * DFF / 4, NEXPX * DMODEL * DFF / 4);
    }

    // 5) down-GEMM, split-K=2, gate-scaled atomic accumulate into out
    {
        dim3 g(DMODEL / 128, 16, NEXPX * 2);
        gemm_tc<<<g, GTHREADS, GEMM_SMEM>>>(Hh, DFF, nullptr,
                                            W2x, (size_t)DMODEL * DFF, b2x, DMODEL,
                                            nullptr, 0,
                                            out, rows_token, growsc,
                                            offsets, DFF, 2, 0,
                                            nullptr, nullptr, nullptr, 0, 0);
    }
}

// round 15
// speedup vs baseline: 1.4239x; 1.4239x over previous
#include <cuda_runtime.h>
#include <cuda_fp16.h>
#include <stdint.h>
#include <math.h>

#define NTOK   4096
#define DMODEL 1024
#define DFF    4096
#define NEXP   8
#define NEXPX  9
#define NASSIGN (NTOK*2)
#define NROWS  (NASSIGN + NTOK)
#define SCALE_F 0.894427190999915878f

// ---------------- device scratch ----------------------------------------------------
__device__ __half d_W1x[(size_t)NEXPX * DFF * DMODEL];
__device__ __half d_W2x[(size_t)NEXPX * DMODEL * DFF];
__device__ float  d_b1x[NEXPX * DFF];
__device__ float  d_b2x[NEXPX * DMODEL];
__device__ __half d_xh[(size_t)NTOK * DMODEL];
__device__ __half d_Hh[(size_t)NROWS * DFF];
__device__ float  d_gates[NASSIGN];
__device__ int    d_assign_e[NASSIGN];
__device__ int    d_offsets[NEXPX + 1];
__device__ int    d_rows_token[NROWS];
__device__ float  d_growsc[NROWS];

// ---------------- helpers --------------------------------------------------------------
__device__ __forceinline__ float gelu_tanh(float v) {
    const float c0 = 0.7978845608028654f;
    const float c1 = 0.044715f;
    float t = tanhf(c0 * (v + c1 * v * v * v));
    return 0.5f * v * (1.0f + t);
}

__device__ __forceinline__ void mma16816(float* c, const uint32_t* a, const uint32_t* b) {
    asm volatile(
        "mma.sync.aligned.m16n8k16.row.col.f32.f16.f16.f32 "
        "{%0,%1,%2,%3}, {%4,%5,%6,%7}, {%8,%9}, {%0,%1,%2,%3};"
        : "+f"(c[0]), "+f"(c[1]), "+f"(c[2]), "+f"(c[3])
        : "r"(a[0]), "r"(a[1]), "r"(a[2]), "r"(a[3]), "r"(b[0]), "r"(b[1]));
}

__device__ __forceinline__ void ldsm4(uint32_t* r, uint32_t addr) {
    asm volatile("ldmatrix.sync.aligned.m8n8.x4.shared.b16 {%0,%1,%2,%3}, [%4];"
                 : "=r"(r[0]), "=r"(r[1]), "=r"(r[2]), "=r"(r[3]) : "r"(addr));
}

__device__ __forceinline__ uint32_t smem_u32(const void* p) {
    uint32_t a;
    asm("{ .reg .u64 t; cvta.to.shared.u64 t, %1; cvt.u32.u64 %0, t; }" : "=r"(a) : "l"(p));
    return a;
}

__device__ __forceinline__ void cp16(uint32_t saddr, const void* g, int srcsz) {
    asm volatile("cp.async.cg.shared.global [%0], [%1], 16, %2;"
                 :: "r"(saddr), "l"(g), "r"(srcsz) : "memory");
}
#define CP_COMMIT() asm volatile("cp.async.commit_group;" ::: "memory")
#define CP_WAIT1()  asm volatile("cp.async.wait_group 1;" ::: "memory")

__device__ __forceinline__ void cvt_store(const float4* __restrict__ src, uint2* __restrict__ dst, int i) {
    float4 v = src[i];
    __half2 a = __floats2half2_rn(v.x, v.y);
    __half2 b = __floats2half2_rn(v.z, v.w);
    dst[i] = make_uint2(*(uint32_t*)&a, *(uint32_t*)&b);
}

// ---------------- launch 1: router + W1/x/bias conversion (fused) -------------------------
#define CVT_BLOCKS 4096
__global__ void router_cvt(const float* __restrict__ x,
                           const float* __restrict__ wr,
                           const float4* __restrict__ W1, const float4* __restrict__ Ws1,
                           const float* __restrict__ b1, const float* __restrict__ bs1,
                           const float* __restrict__ b2, const float* __restrict__ bs2,
                           uint2* __restrict__ W1x, uint2* __restrict__ xh,
                           float* __restrict__ b1x, float* __restrict__ b2x) {
    if (blockIdx.x >= NTOK) {
        int idx0 = (blockIdx.x - NTOK) * blockDim.x + threadIdx.x;
        const int nthr = CVT_BLOCKS * 256;
        const int n4r = NEXP * DFF * DMODEL / 4;
        const int n4t = NEXPX * DFF * DMODEL / 4;
        for (int i = idx0; i < n4t; i += nthr) {
            float4 v = (i < n4r) ? W1[i] : Ws1[i - n4r];
            __half2 a = __floats2half2_rn(v.x, v.y);
            __half2 b = __floats2half2_rn(v.z, v.w);
            W1x[i] = make_uint2(*(uint32_t*)&a, *(uint32_t*)&b);
        }
        for (int i = idx0; i < NTOK * DMODEL / 4; i += nthr)
            cvt_store((const float4*)x, xh, i);
        for (int i = idx0; i < NEXPX * DFF; i += nthr)
            b1x[i] = (i < NEXP * DFF) ? b1[i] : bs1[i - NEXP * DFF];
        for (int i = idx0; i < NEXPX * DMODEL; i += nthr)
            b2x[i] = (i < NEXP * DMODEL) ? b2[i] : bs2[i - NEXP * DMODEL];
        return;
    }
    int t = blockIdx.x;
    int warp = threadIdx.x >> 5;
    int lane = threadIdx.x & 31;
    const float* xr = x + (size_t)t * DMODEL;
    const float* w  = wr + (size_t)warp * DMODEL;
    float s = 0.f;
    #pragma unroll 4
    for (int i = lane; i < DMODEL; i += 32) s += xr[i] * w[i];
    #pragma unroll
    for (int o = 16; o > 0; o >>= 1) s += __shfl_xor_sync(0xFFFFFFFFu, s, o);

    __shared__ float logits[NEXP];
    if (warp < NEXP && lane == 0) logits[warp] = s;
    __syncthreads();

    if (threadIdx.x == 0) {
        float mx = logits[0];
        #pragma unroll
        for (int e = 1; e < NEXP; e++) mx = fmaxf(mx, logits[e]);
        float p[NEXP]; float sum = 0.f;
        #pragma unroll
        for (int e = 0; e < NEXP; e++) { p[e] = expf(logits[e] - mx); sum += p[e]; }
        float inv = 1.f / sum;
        #pragma unroll
        for (int e = 0; e < NEXP; e++) p[e] *= inv;
        int i0 = 0;
        #pragma unroll
        for (int e = 1; e < NEXP; e++) if (p[e] > p[i0]) i0 = e;
        int i1 = -1;
        #pragma unroll
        for (int e = 0; e < NEXP; e++) {
            if (e == i0) continue;
            if (i1 < 0 || p[e] > p[i1]) i1 = e;
        }
        d_gates[2 * t + 0] = p[i0];
        d_gates[2 * t + 1] = p[i1];
        d_assign_e[2 * t + 0] = i0;
        d_assign_e[2 * t + 1] = i1;
    }
}

// ---------------- launch 2: single-block count + scan + place ----------------------------
__global__ void scanplace_kernel() {
    __shared__ int scount[NEXP];
    __shared__ int scursor[NEXP];
    int tid = threadIdx.x;
    if (tid < NEXP) scount[tid] = 0;
    __syncthreads();
    for (int a = tid; a < NASSIGN; a += blockDim.x)
        atomicAdd(&scount[d_assign_e[a]], 1);
    __syncthreads();
    if (tid == 0) {
        int s = 0;
        for (int e = 0; e < NEXP; e++) { d_offsets[e] = s; scursor[e] = s; s += scount[e]; }
        d_offsets[NEXP]  = s;
        d_offsets[NEXPX] = NROWS;
    }
    __syncthreads();
    for (int a = tid; a < NASSIGN; a += blockDim.x) {
        int e = d_assign_e[a];
        int r = atomicAdd(&scursor[e], 1);
        d_rows_token[r] = a >> 1;
        d_growsc[r] = SCALE_F * d_gates[a];
    }
    for (int t = tid; t < NTOK; t += blockDim.x) {
        d_rows_token[NASSIGN + t] = t;
        d_growsc[NASSIGN + t] = SCALE_F;
    }
}

// ================= fp16 HMMA grouped GEMM: 256x128x64, 512 thr, frag-pipelined ===========
// (R12 proven core) Warp grid 4x4, warp tile 64x32, cp.async 3-stage.
#define RS      144
#define T_B     36864             // A: 256 rows x 144B
#define STAGE_B 55296             // + B: 128 rows x 144B
#define NSTAGE  3
#define GEMM_SMEM (NSTAGE * STAGE_B)
#define GTHREADS 512

__global__ __launch_bounds__(GTHREADS, 1)
void gemm_tc(const __half* __restrict__ Ah, int lda, const int* __restrict__ gather,
             const __half* __restrict__ Bh_base, size_t wstride,
             const float* __restrict__ bias_base, size_t bstride,
             __half* __restrict__ Ch, int ldc,
             float* __restrict__ out_at,
             const int* __restrict__ rows_token, const float* __restrict__ growsc,
             const int* __restrict__ offs, int K, int kh_count, int do_gelu,
             const float4* __restrict__ cw8, const float4* __restrict__ cws,
             uint2* __restrict__ cdst, int cn4r, int cn4t)
{
    extern __shared__ char smem[];
    int z = blockIdx.z;
    int nz_gemm = NEXPX * kh_count;
    if (z >= nz_gemm) {
        int idx0 = (blockIdx.y * gridDim.x + blockIdx.x) * blockDim.x + threadIdx.x;
        int nthr = gridDim.x * gridDim.y * blockDim.x;
        for (int i = idx0; i < cn4t; i += nthr) {
            float4 v = (i < cn4r) ? cw8[i] : cws[i - cn4r];
            __half2 a = __floats2half2_rn(v.x, v.y);
            __half2 b = __floats2half2_rn(v.z, v.w);
            cdst[i] = make_uint2(*(uint32_t*)&a, *(uint32_t*)&b);
        }
        return;
    }
    int e  = z / kh_count;
    int kh = z - e * kh_count;
    int Ks = K / kh_count;
    int lo = offs[e];
    int hi = offs[e + 1];
    int m0 = lo + blockIdx.y * 256;
    if (m0 >= hi) return;
    int n0 = blockIdx.x * 128;
    const __half* Bh = Bh_base + (size_t)e * wstride + kh * Ks;
    const float* bias = bias_base + (size_t)e * bstride;

    uint32_t sbase = smem_u32(smem);
    int tid  = threadIdx.x;
    int wid  = tid >> 5;
    int lane = tid & 31;
    int tig  = lane & 3;
    int wm   = wid >> 2;
    int wn   = wid & 3;

    // ---- cp.async coords ----------------------------------------------------------------
    const char* pA[4]; int avv[4]; uint32_t sAo[4];
    #pragma unroll
    for (int j = 0; j < 4; j++) {
        int idx = tid + j * GTHREADS;
        int row = idx >> 3;
        int cb  = (idx & 7) * 16;
        int arow = m0 + row;
        avv[j] = (arow < hi) ? 16 : 0;
        int asrc = (arow < hi) ? (gather ? gather[arow] : arow) : 0;
        pA[j] = (const char*)(Ah + (size_t)asrc * lda + kh * Ks) + cb;
        sAo[j] = sbase + (uint32_t)(row * RS + cb);
    }
    const char* pB[2]; uint32_t sBo[2];
    #pragma unroll
    for (int j = 0; j < 2; j++) {
        int idx = tid + j * GTHREADS;
        int row = idx >> 3;
        int cb  = (idx & 7) * 16;
        pB[j] = (const char*)(Bh + (size_t)(n0 + row) * K) + cb;
        sBo[j] = sbase + (uint32_t)(T_B + row * RS + cb);
    }

    // ---- ldmatrix lane offsets ----------------------------------------------------------
    uint32_t aoff[4], boff[4];
    #pragma unroll
    for (int mi = 0; mi < 4; mi++)
        aoff[mi] = (uint32_t)((wm * 64 + mi * 16 + (lane & 15)) * RS + (lane >> 4) * 16);
    #pragma unroll
    for (int ni = 0; ni < 4; ni++)
        boff[ni] = (uint32_t)(T_B + (wn * 32 + ni * 8 + (lane & 7)) * RS + (lane >> 3) * 16);

    float acc[4][4][4];
    #pragma unroll
    for (int mi = 0; mi < 4; mi++)
        #pragma unroll
        for (int ni = 0; ni < 4; ni++)
            #pragma unroll
            for (int q = 0; q < 4; q++) acc[mi][ni][q] = 0.f;

    int nk = Ks >> 6;

    auto issue = [&](int kt, int s) {
        uint32_t so = (uint32_t)(s * STAGE_B);
        int kbyte = kt << 7;
        #pragma unroll
        for (int j = 0; j < 4; j++) cp16(sAo[j] + so, pA[j] + kbyte, avv[j]);
        #pragma unroll
        for (int j = 0; j < 2; j++) cp16(sBo[j] + so, pB[j] + kbyte, 16);
        CP_COMMIT();
    };

    issue(0, 0);
    if (nk > 1) issue(1, 1); else CP_COMMIT();

    int s = 0;
    for (int kt = 0; kt < nk; kt++) {
        CP_WAIT1();
        __syncthreads();

        if (kt + 2 < nk) issue(kt + 2, (s + 2) % NSTAGE);
        else CP_COMMIT();

        uint32_t st = sbase + (uint32_t)(s * STAGE_B);

        uint32_t bhf[4][4];
        uint32_t ahf[2][4][4];
        #pragma unroll
        for (int ni = 0; ni < 4; ni++) ldsm4(bhf[ni], st + boff[ni]);
        #pragma unroll
        for (int mi = 0; mi < 4; mi++) ldsm4(ahf[0][mi], st + aoff[mi]);

        #pragma unroll
        for (int ks = 0; ks < 4; ks++) {
            int cur = ks & 1;
            #pragma unroll
            for (int mi = 0; mi < 4; mi++)
                #pragma unroll
                for (int ni = 0; ni < 4; ni++)
                    mma16816(acc[mi][ni], ahf[cur][mi], &bhf[ni][2 * (ks & 1)]);
            if (ks == 1) {
                #pragma unroll
                for (int ni = 0; ni < 4; ni++) ldsm4(bhf[ni], st + boff[ni] + 64);
            }
            if (ks < 3) {
                #pragma unroll
                for (int mi = 0; mi < 4; mi++) ldsm4(ahf[cur ^ 1][mi], st + aoff[mi] + (ks + 1) * 32);
            }
        }

        s = (s + 1) % NSTAGE;
    }

    // ---------------- epilogue ------------------------------------------------------------
    int g = lane >> 2;
    #pragma unroll
    for (int mi = 0; mi < 4; mi++) {
        int row0 = m0 + wm * 64 + mi * 16 + g;
        #pragma unroll
        for (int h = 0; h < 2; h++) {
            int row = row0 + h * 8;
            if (row >= hi) continue;
            if (Ch) {
                #pragma unroll
                for (int ni = 0; ni < 4; ni++) {
                    int cn = n0 + wn * 32 + ni * 8 + tig * 2;
                    float v0 = acc[mi][ni][2 * h + 0] + bias[cn];
                    float v1 = acc[mi][ni][2 * h + 1] + bias[cn + 1];
                    if (do_gelu) { v0 = gelu_tanh(v0); v1 = gelu_tanh(v1); }
                    __half2 hp = __floats2half2_rn(v0, v1);
                    *(uint32_t*)(Ch + (size_t)row * ldc + cn) = *(uint32_t*)&hp;
                }
            } else {
                int tok = rows_token[row];
                float gs = growsc[row];
                float* ob = out_at + (size_t)tok * DMODEL;
                #pragma unroll
                for (int ni = 0; ni < 4; ni++) {
                    int cn = n0 + wn * 32 + ni * 8 + tig * 2;
                    float b0 = (kh == 0) ? bias[cn]     : 0.f;
                    float b1 = (kh == 0) ? bias[cn + 1] : 0.f;
                    atomicAdd(ob + cn,     gs * (acc[mi][ni][2 * h + 0] + b0));
                    atomicAdd(ob + cn + 1, gs * (acc[mi][ni][2 * h + 1] + b1));
                }
            }
        }
    }
}

// ---------------- launcher --------------------------------------------------------------------
extern "C" void kernel_launch(void* const* d_in, const int* in_sizes, int n_in,
                              void* d_out, int out_size)
{
    const float* x   = (const float*)d_in[0];
    const float* wr  = (const float*)d_in[1];
    const float* W1  = (const float*)d_in[2];
    const float* b1  = (const float*)d_in[3];
    const float* W2  = (const float*)d_in[4];
    const float* b2  = (const float*)d_in[5];
    const float* Ws1 = (const float*)d_in[6];
    const float* bs1 = (const float*)d_in[7];
    const float* Ws2 = (const float*)d_in[8];
    const float* bs2 = (const float*)d_in[9];
    float* out = (float*)d_out;

    __half *W1x, *W2x, *xh, *Hh;
    float *b1x, *b2x, *growsc;
    int *offsets, *rows_token;
    cudaGetSymbolAddress((void**)&W1x, d_W1x);
    cudaGetSymbolAddress((void**)&W2x, d_W2x);
    cudaGetSymbolAddress((void**)&b1x, d_b1x);
    cudaGetSymbolAddress((void**)&b2x, d_b2x);
    cudaGetSymbolAddress((void**)&xh, d_xh);
    cudaGetSymbolAddress((void**)&Hh, d_Hh);
    cudaGetSymbolAddress((void**)&growsc, d_growsc);
    cudaGetSymbolAddress((void**)&offsets, d_offsets);
    cudaGetSymbolAddress((void**)&rows_token, d_rows_token);

    cudaFuncSetAttribute(gemm_tc, cudaFuncAttributeMaxDynamicSharedMemorySize, GEMM_SMEM);

    // 1) router + W1/x/bias conversion (fused, overlapped)
    router_cvt<<<NTOK + CVT_BLOCKS, 256>>>(x, wr,
                                           (const float4*)W1, (const float4*)Ws1,
                                           b1, bs1, b2, bs2,
                                           (uint2*)W1x, (uint2*)xh, b1x, b2x);

    // 2) scan + place + gate-scale table
    scanplace_kernel<<<1, 1024>>>();

    // 3) zero output
    cudaMemsetAsync(out, 0, (size_t)NTOK * DMODEL * sizeof(float));

    // 4) up-GEMM (z=0..8) + fused W2 conversion (z=9)
    {
        dim3 g(DFF / 128, 16, NEXPX + 1);
        gemm_tc<<<g, GTHREADS, GEMM_SMEM>>>(xh, DMODEL, rows_token,
                                            W1x, (size_t)DFF * DMODEL, b1x, DFF,
                                            Hh, DFF,
                                            nullptr, nullptr, nullptr,
                                            offsets, DMODEL, 1, 1,
                                            (const float4*)W2, (const float4*)Ws2, (uint2*)W2x,
                                            NEXP * DMODEL * DFF / 4, NEXPX * DMODEL * DFF / 4);
    }

    // 5) down-GEMM, split-K=4, gate-scaled atomic accumulate into out
    {
        dim3 g(DMODEL / 128, 16, NEXPX * 4);
        gemm_tc<<<g, GTHREADS, GEMM_SMEM>>>(Hh, DFF, nullptr,
                                            W2x, (size_t)DMODEL * DFF, b2x, DMODEL,
                                            nullptr, 0,
                                            out, rows_token, growsc,
                                            offsets, DFF, 4, 0,
                                            nullptr, nullptr, nullptr, 0, 0);
    }
}

// round 16
// speedup vs baseline: 1.4499x; 1.0182x over previous
#include <cuda_runtime.h>
#include <cuda_fp16.h>
#include <stdint.h>
#include <math.h>

#define NTOK   4096
#define DMODEL 1024
#define DFF    4096
#define NEXP   8
#define NEXPX  9
#define NASSIGN (NTOK*2)
#define NROWS  (NASSIGN + NTOK)
#define SCALE_F 0.894427190999915878f

// ---------------- device scratch ----------------------------------------------------
__device__ __half d_W1x[(size_t)NEXPX * DFF * DMODEL];
__device__ __half d_W2x[(size_t)NEXPX * DMODEL * DFF];
__device__ float  d_b1x[NEXPX * DFF];
__device__ float  d_b2x[NEXPX * DMODEL];
__device__ __half d_xh[(size_t)NTOK * DMODEL];
__device__ __half d_Hh[(size_t)NROWS * DFF];
__device__ float  d_ybuf[(size_t)2 * NROWS * DMODEL];   // two split-K planes
__device__ float  d_gates[NASSIGN];
__device__ int    d_assign_e[NASSIGN];
__device__ int    d_offsets[NEXPX + 1];
__device__ int    d_rows_token[NROWS];
__device__ int    d_rowof[NASSIGN];

// ---------------- helpers --------------------------------------------------------------
__device__ __forceinline__ float gelu_tanh(float v) {
    const float c0 = 0.7978845608028654f;
    const float c1 = 0.044715f;
    float t = tanhf(c0 * (v + c1 * v * v * v));
    return 0.5f * v * (1.0f + t);
}

__device__ __forceinline__ void mma16816(float* c, const uint32_t* a, const uint32_t* b) {
    asm volatile(
        "mma.sync.aligned.m16n8k16.row.col.f32.f16.f16.f32 "
        "{%0,%1,%2,%3}, {%4,%5,%6,%7}, {%8,%9}, {%0,%1,%2,%3};"
        : "+f"(c[0]), "+f"(c[1]), "+f"(c[2]), "+f"(c[3])
        : "r"(a[0]), "r"(a[1]), "r"(a[2]), "r"(a[3]), "r"(b[0]), "r"(b[1]));
}

__device__ __forceinline__ void ldsm4(uint32_t* r, uint32_t addr) {
    asm volatile("ldmatrix.sync.aligned.m8n8.x4.shared.b16 {%0,%1,%2,%3}, [%4];"
                 : "=r"(r[0]), "=r"(r[1]), "=r"(r[2]), "=r"(r[3]) : "r"(addr));
}

__device__ __forceinline__ uint32_t smem_u32(const void* p) {
    uint32_t a;
    asm("{ .reg .u64 t; cvta.to.shared.u64 t, %1; cvt.u32.u64 %0, t; }" : "=r"(a) : "l"(p));
    return a;
}

__device__ __forceinline__ void cp16(uint32_t saddr, const void* g, int srcsz) {
    asm volatile("cp.async.cg.shared.global [%0], [%1], 16, %2;"
                 :: "r"(saddr), "l"(g), "r"(srcsz) : "memory");
}
#define CP_COMMIT() asm volatile("cp.async.commit_group;" ::: "memory")
#define CP_WAIT1()  asm volatile("cp.async.wait_group 1;" ::: "memory")

__device__ __forceinline__ void cvt_store(const float4* __restrict__ src, uint2* __restrict__ dst, int i) {
    float4 v = src[i];
    __half2 a = __floats2half2_rn(v.x, v.y);
    __half2 b = __floats2half2_rn(v.z, v.w);
    dst[i] = make_uint2(*(uint32_t*)&a, *(uint32_t*)&b);
}

// ---------------- launch 1: router + W1/x/bias conversion (fused) -------------------------
#define CVT_BLOCKS 4096
__global__ void router_cvt(const float* __restrict__ x,
                           const float* __restrict__ wr,
                           const float4* __restrict__ W1, const float4* __restrict__ Ws1,
                           const float* __restrict__ b1, const float* __restrict__ bs1,
                           const float* __restrict__ b2, const float* __restrict__ bs2,
                           uint2* __restrict__ W1x, uint2* __restrict__ xh,
                           float* __restrict__ b1x, float* __restrict__ b2x) {
    if (blockIdx.x >= NTOK) {
        int idx0 = (blockIdx.x - NTOK) * blockDim.x + threadIdx.x;
        const int nthr = CVT_BLOCKS * 256;
        const int n4r = NEXP * DFF * DMODEL / 4;
        const int n4t = NEXPX * DFF * DMODEL / 4;
        for (int i = idx0; i < n4t; i += nthr) {
            float4 v = (i < n4r) ? W1[i] : Ws1[i - n4r];
            __half2 a = __floats2half2_rn(v.x, v.y);
            __half2 b = __floats2half2_rn(v.z, v.w);
            W1x[i] = make_uint2(*(uint32_t*)&a, *(uint32_t*)&b);
        }
        for (int i = idx0; i < NTOK * DMODEL / 4; i += nthr)
            cvt_store((const float4*)x, xh, i);
        for (int i = idx0; i < NEXPX * DFF; i += nthr)
            b1x[i] = (i < NEXP * DFF) ? b1[i] : bs1[i - NEXP * DFF];
        for (int i = idx0; i < NEXPX * DMODEL; i += nthr)
            b2x[i] = (i < NEXP * DMODEL) ? b2[i] : bs2[i - NEXP * DMODEL];
        return;
    }
    int t = blockIdx.x;
    int warp = threadIdx.x >> 5;
    int lane = threadIdx.x & 31;
    const float* xr = x + (size_t)t * DMODEL;
    const float* w  = wr + (size_t)warp * DMODEL;
    float s = 0.f;
    #pragma unroll 4
    for (int i = lane; i < DMODEL; i += 32) s += xr[i] * w[i];
    #pragma unroll
    for (int o = 16; o > 0; o >>= 1) s += __shfl_xor_sync(0xFFFFFFFFu, s, o);

    __shared__ float logits[NEXP];
    if (warp < NEXP && lane == 0) logits[warp] = s;
    __syncthreads();

    if (threadIdx.x == 0) {
        float mx = logits[0];
        #pragma unroll
        for (int e = 1; e < NEXP; e++) mx = fmaxf(mx, logits[e]);
        float p[NEXP]; float sum = 0.f;
        #pragma unroll
        for (int e = 0; e < NEXP; e++) { p[e] = expf(logits[e] - mx); sum += p[e]; }
        float inv = 1.f / sum;
        #pragma unroll
        for (int e = 0; e < NEXP; e++) p[e] *= inv;
        int i0 = 0;
        #pragma unroll
        for (int e = 1; e < NEXP; e++) if (p[e] > p[i0]) i0 = e;
        int i1 = -1;
        #pragma unroll
        for (int e = 0; e < NEXP; e++) {
            if (e == i0) continue;
            if (i1 < 0 || p[e] > p[i1]) i1 = e;
        }
        d_gates[2 * t + 0] = p[i0];
        d_gates[2 * t + 1] = p[i1];
        d_assign_e[2 * t + 0] = i0;
        d_assign_e[2 * t + 1] = i1;
    }
}

// ---------------- launch 2: single-block count + scan + place ----------------------------
__global__ void scanplace_kernel() {
    __shared__ int scount[NEXP];
    __shared__ int scursor[NEXP];
    int tid = threadIdx.x;
    if (tid < NEXP) scount[tid] = 0;
    __syncthreads();
    for (int a = tid; a < NASSIGN; a += blockDim.x)
        atomicAdd(&scount[d_assign_e[a]], 1);
    __syncthreads();
    if (tid == 0) {
        int s = 0;
        for (int e = 0; e < NEXP; e++) { d_offsets[e] = s; scursor[e] = s; s += scount[e]; }
        d_offsets[NEXP]  = s;
        d_offsets[NEXPX] = NROWS;
    }
    __syncthreads();
    for (int a = tid; a < NASSIGN; a += blockDim.x) {
        int e = d_assign_e[a];
        int r = atomicAdd(&scursor[e], 1);
        d_rows_token[r] = a >> 1;
        d_rowof[a] = r;
    }
    for (int t = tid; t < NTOK; t += blockDim.x)
        d_rows_token[NASSIGN + t] = t;
}

// ================= fp16 HMMA grouped GEMM: 256x128x64, 512 thr, frag-pipelined ===========
// (R12 proven core) Warp grid 4x4, warp tile 64x32, cp.async 3-stage.
#define RS      144
#define T_B     36864
#define STAGE_B 55296
#define NSTAGE  3
#define GEMM_SMEM (NSTAGE * STAGE_B)
#define GTHREADS 512

__global__ __launch_bounds__(GTHREADS, 1)
void gemm_tc(const __half* __restrict__ Ah, int lda, const int* __restrict__ gather,
             const __half* __restrict__ Bh_base, size_t wstride,
             const float* __restrict__ bias_base, size_t bstride,
             __half* __restrict__ Ch, int ldc,
             float* __restrict__ ybuf,
             const int* __restrict__ offs, int K, int kh_count, int do_gelu,
             const float4* __restrict__ cw8, const float4* __restrict__ cws,
             uint2* __restrict__ cdst, int cn4r, int cn4t)
{
    extern __shared__ char smem[];
    int z = blockIdx.z;
    int nz_gemm = NEXPX * kh_count;
    if (z >= nz_gemm) {
        int idx0 = (blockIdx.y * gridDim.x + blockIdx.x) * blockDim.x + threadIdx.x;
        int nthr = gridDim.x * gridDim.y * blockDim.x;
        for (int i = idx0; i < cn4t; i += nthr) {
            float4 v = (i < cn4r) ? cw8[i] : cws[i - cn4r];
            __half2 a = __floats2half2_rn(v.x, v.y);
            __half2 b = __floats2half2_rn(v.z, v.w);
            cdst[i] = make_uint2(*(uint32_t*)&a, *(uint32_t*)&b);
        }
        return;
    }
    int e  = z / kh_count;
    int kh = z - e * kh_count;
    int Ks = K / kh_count;
    int lo = offs[e];
    int hi = offs[e + 1];
    int m0 = lo + blockIdx.y * 256;
    if (m0 >= hi) return;
    int n0 = blockIdx.x * 128;
    const __half* Bh = Bh_base + (size_t)e * wstride + kh * Ks;
    const float* bias = bias_base + (size_t)e * bstride;

    uint32_t sbase = smem_u32(smem);
    int tid  = threadIdx.x;
    int wid  = tid >> 5;
    int lane = tid & 31;
    int tig  = lane & 3;
    int wm   = wid >> 2;
    int wn   = wid & 3;

    // ---- cp.async coords ----------------------------------------------------------------
    const char* pA[4]; int avv[4]; uint32_t sAo[4];
    #pragma unroll
    for (int j = 0; j < 4; j++) {
        int idx = tid + j * GTHREADS;
        int row = idx >> 3;
        int cb  = (idx & 7) * 16;
        int arow = m0 + row;
        avv[j] = (arow < hi) ? 16 : 0;
        int asrc = (arow < hi) ? (gather ? gather[arow] : arow) : 0;
        pA[j] = (const char*)(Ah + (size_t)asrc * lda + kh * Ks) + cb;
        sAo[j] = sbase + (uint32_t)(row * RS + cb);
    }
    const char* pB[2]; uint32_t sBo[2];
    #pragma unroll
    for (int j = 0; j < 2; j++) {
        int idx = tid + j * GTHREADS;
        int row = idx >> 3;
        int cb  = (idx & 7) * 16;
        pB[j] = (const char*)(Bh + (size_t)(n0 + row) * K) + cb;
        sBo[j] = sbase + (uint32_t)(T_B + row * RS + cb);
    }

    // ---- ldmatrix lane offsets ----------------------------------------------------------
    uint32_t aoff[4], boff[4];
    #pragma unroll
    for (int mi = 0; mi < 4; mi++)
        aoff[mi] = (uint32_t)((wm * 64 + mi * 16 + (lane & 15)) * RS + (lane >> 4) * 16);
    #pragma unroll
    for (int ni = 0; ni < 4; ni++)
        boff[ni] = (uint32_t)(T_B + (wn * 32 + ni * 8 + (lane & 7)) * RS + (lane >> 3) * 16);

    float acc[4][4][4];
    #pragma unroll
    for (int mi = 0; mi < 4; mi++)
        #pragma unroll
        for (int ni = 0; ni < 4; ni++)
            #pragma unroll
            for (int q = 0; q < 4; q++) acc[mi][ni][q] = 0.f;

    int nk = Ks >> 6;

    auto issue = [&](int kt, int s) {
        uint32_t so = (uint32_t)(s * STAGE_B);
        int kbyte = kt << 7;
        #pragma unroll
        for (int j = 0; j < 4; j++) cp16(sAo[j] + so, pA[j] + kbyte, avv[j]);
        #pragma unroll
        for (int j = 0; j < 2; j++) cp16(sBo[j] + so, pB[j] + kbyte, 16);
        CP_COMMIT();
    };

    issue(0, 0);
    if (nk > 1) issue(1, 1); else CP_COMMIT();

    int s = 0;
    for (int kt = 0; kt < nk; kt++) {
        CP_WAIT1();
        __syncthreads();

        if (kt + 2 < nk) issue(kt + 2, (s + 2) % NSTAGE);
        else CP_COMMIT();

        uint32_t st = sbase + (uint32_t)(s * STAGE_B);

        uint32_t bhf[4][4];
        uint32_t ahf[2][4][4];
        #pragma unroll
        for (int ni = 0; ni < 4; ni++) ldsm4(bhf[ni], st + boff[ni]);
        #pragma unroll
        for (int mi = 0; mi < 4; mi++) ldsm4(ahf[0][mi], st + aoff[mi]);

        #pragma unroll
        for (int ks = 0; ks < 4; ks++) {
            int cur = ks & 1;
            #pragma unroll
            for (int mi = 0; mi < 4; mi++)
                #pragma unroll
                for (int ni = 0; ni < 4; ni++)
                    mma16816(acc[mi][ni], ahf[cur][mi], &bhf[ni][2 * (ks & 1)]);
            if (ks == 1) {
                #pragma unroll
                for (int ni = 0; ni < 4; ni++) ldsm4(bhf[ni], st + boff[ni] + 64);
            }
            if (ks < 3) {
                #pragma unroll
                for (int mi = 0; mi < 4; mi++) ldsm4(ahf[cur ^ 1][mi], st + aoff[mi] + (ks + 1) * 32);
            }
        }

        s = (s + 1) % NSTAGE;
    }

    // ---------------- epilogue ------------------------------------------------------------
    int g = lane >> 2;
    #pragma unroll
    for (int mi = 0; mi < 4; mi++) {
        int row0 = m0 + wm * 64 + mi * 16 + g;
        #pragma unroll
        for (int h = 0; h < 2; h++) {
            int row = row0 + h * 8;
            if (row >= hi) continue;
            if (Ch) {
                #pragma unroll
                for (int ni = 0; ni < 4; ni++) {
                    int cn = n0 + wn * 32 + ni * 8 + tig * 2;
                    float v0 = acc[mi][ni][2 * h + 0] + bias[cn];
                    float v1 = acc[mi][ni][2 * h + 1] + bias[cn + 1];
                    if (do_gelu) { v0 = gelu_tanh(v0); v1 = gelu_tanh(v1); }
                    __half2 hp = __floats2half2_rn(v0, v1);
                    *(uint32_t*)(Ch + (size_t)row * ldc + cn) = *(uint32_t*)&hp;
                }
            } else {
                // split-K plane store (deterministic, no atomics)
                float* ob = ybuf + (size_t)kh * NROWS * DMODEL + (size_t)row * DMODEL;
                #pragma unroll
                for (int ni = 0; ni < 4; ni++) {
                    int cn = n0 + wn * 32 + ni * 8 + tig * 2;
                    float b0 = (kh == 0) ? bias[cn]     : 0.f;
                    float b1 = (kh == 0) ? bias[cn + 1] : 0.f;
                    *(float2*)(ob + cn) = make_float2(acc[mi][ni][2 * h + 0] + b0,
                                                      acc[mi][ni][2 * h + 1] + b1);
                }
            }
        }
    }
}

// ---------------- launch 6: combine (sum split-K planes, gates, SCALE) ---------------------
__global__ void combine_kernel(float* __restrict__ out) {
    int t = blockIdx.x;
    float g0 = d_gates[2 * t + 0];
    float g1 = d_gates[2 * t + 1];
    size_t r0 = (size_t)d_rowof[2 * t + 0] * DMODEL;
    size_t r1 = (size_t)d_rowof[2 * t + 1] * DMODEL;
    size_t rs = (size_t)(NASSIGN + t) * DMODEL;
    const size_t P = (size_t)NROWS * DMODEL;
    float* o = out + (size_t)t * DMODEL;
    for (int d = threadIdx.x * 4; d < DMODEL; d += blockDim.x * 4) {
        float4 s0 = *(const float4*)(d_ybuf + rs + d);
        float4 s1 = *(const float4*)(d_ybuf + P + rs + d);
        float4 a0 = *(const float4*)(d_ybuf + r0 + d);
        float4 a1 = *(const float4*)(d_ybuf + P + r0 + d);
        float4 b0 = *(const float4*)(d_ybuf + r1 + d);
        float4 b1 = *(const float4*)(d_ybuf + P + r1 + d);
        float4 ov;
        ov.x = SCALE_F * ((s0.x + s1.x) + g0 * (a0.x + a1.x) + g1 * (b0.x + b1.x));
        ov.y = SCALE_F * ((s0.y + s1.y) + g0 * (a0.y + a1.y) + g1 * (b0.y + b1.y));
        ov.z = SCALE_F * ((s0.z + s1.z) + g0 * (a0.z + a1.z) + g1 * (b0.z + b1.z));
        ov.w = SCALE_F * ((s0.w + s1.w) + g0 * (a0.w + a1.w) + g1 * (b0.w + b1.w));
        *(float4*)(o + d) = ov;
    }
}

// ---------------- launcher --------------------------------------------------------------------
extern "C" void kernel_launch(void* const* d_in, const int* in_sizes, int n_in,
                              void* d_out, int out_size)
{
    const float* x   = (const float*)d_in[0];
    const float* wr  = (const float*)d_in[1];
    const float* W1  = (const float*)d_in[2];
    const float* b1  = (const float*)d_in[3];
    const float* W2  = (const float*)d_in[4];
    const float* b2  = (const float*)d_in[5];
    const float* Ws1 = (const float*)d_in[6];
    const float* bs1 = (const float*)d_in[7];
    const float* Ws2 = (const float*)d_in[8];
    const float* bs2 = (const float*)d_in[9];
    float* out = (float*)d_out;

    __half *W1x, *W2x, *xh, *Hh;
    float *b1x, *b2x, *ybuf;
    int *offsets, *rows_token;
    cudaGetSymbolAddress((void**)&W1x, d_W1x);
    cudaGetSymbolAddress((void**)&W2x, d_W2x);
    cudaGetSymbolAddress((void**)&b1x, d_b1x);
    cudaGetSymbolAddress((void**)&b2x, d_b2x);
    cudaGetSymbolAddress((void**)&xh, d_xh);
    cudaGetSymbolAddress((void**)&Hh, d_Hh);
    cudaGetSymbolAddress((void**)&ybuf, d_ybuf);
    cudaGetSymbolAddress((void**)&offsets, d_offsets);
    cudaGetSymbolAddress((void**)&rows_token, d_rows_token);

    cudaFuncSetAttribute(gemm_tc, cudaFuncAttributeMaxDynamicSharedMemorySize, GEMM_SMEM);

    // 1) router + W1/x/bias conversion (fused, overlapped)
    router_cvt<<<NTOK + CVT_BLOCKS, 256>>>(x, wr,
                                           (const float4*)W1, (const float4*)Ws1,
                                           b1, bs1, b2, bs2,
                                           (uint2*)W1x, (uint2*)xh, b1x, b2x);

    // 2) scan + place
    scanplace_kernel<<<1, 1024>>>();

    // 3) up-GEMM (z=0..8) + fused W2 conversion (z=9)
    {
        dim3 g(DFF / 128, 16, NEXPX + 1);
        gemm_tc<<<g, GTHREADS, GEMM_SMEM>>>(xh, DMODEL, rows_token,
                                            W1x, (size_t)DFF * DMODEL, b1x, DFF,
                                            Hh, DFF,
                                            nullptr,
                                            offsets, DMODEL, 1, 1,
                                            (const float4*)W2, (const float4*)Ws2, (uint2*)W2x,
                                            NEXP * DMODEL * DFF / 4, NEXPX * DMODEL * DFF / 4);
    }

    // 4) down-GEMM, split-K=2, plane stores (no atomics)
    {
        dim3 g(DMODEL / 128, 16, NEXPX * 2);
        gemm_tc<<<g, GTHREADS, GEMM_SMEM>>>(Hh, DFF, nullptr,
                                            W2x, (size_t)DMODEL * DFF, b2x, DMODEL,
                                            nullptr, 0,
                                            ybuf,
                                            offsets, DFF, 2, 0,
                                            nullptr, nullptr, nullptr, 0, 0);
    }

    // 5) combine
    combine_kernel<<<NTOK, 256>>>(out);
}